// round 15
// baseline (speedup 1.0000x reference)
#include <cuda_runtime.h>
#include <math.h>
#include <stdint.h>

// Problem constants
#define SV 512      // source length == target length
#define EV 512      // embed dim
#define HV 1024     // hidden dim
#define G4 4096     // 4*H
#define VV 32000    // vocab
#define NVT 250     // number of 128-wide V tiles (32000/128)

// ---------------- scratch (static device globals; no allocation) ----------
__device__ float    g_Xe[SV * G4];      // enc: x@Wih^T + bih + bhh  [512,4096]
__device__ float    g_Xd[SV * G4];      // dec: same
__device__ float    g_hbuf[2 * HV];     // double-buffered h
__device__ float    g_hs[SV * HV];      // decoder hidden states [512,1024]
__device__ float    g_redm[SV * NVT];   // per-(t, vtile) local max
__device__ float    g_reds[SV * NVT];   // per-(t, vtile) local sumexp
__device__ unsigned g_bar;              // single barrier counter

// ---------------- f32x2 packed FMA helpers (Blackwell FFMA2) --------------
__device__ __forceinline__ unsigned long long dup_f32(float x) {
    unsigned long long r;
    asm("mov.b64 %0, {%1, %1};" : "=l"(r) : "f"(x));
    return r;
}
__device__ __forceinline__ void fma_f32x2(unsigned long long& d,
                                          unsigned long long a,
                                          unsigned long long b) {
    asm("fma.rn.f32x2 %0, %1, %2, %0;" : "+l"(d) : "l"(a), "l"(b));
}
__device__ __forceinline__ float2 unpack2(unsigned long long v) {
    float2 r;
    asm("mov.b64 {%0, %1}, %2;" : "=f"(r.x), "=f"(r.y) : "l"(v));
    return r;
}
// ---------------- fast activations (validated R10/R13) --------------------
__device__ __forceinline__ float tanh_fast(float x) {
    float r;
    asm("tanh.approx.f32 %0, %1;" : "=f"(r) : "f"(x));
    return r;
}
__device__ __forceinline__ float sigmoid_fast(float x) {
    return __fdividef(1.f, 1.f + __expf(-x));
}
// ---------------- tf32 tensor-core helpers --------------------------------
__device__ __forceinline__ uint32_t f2tf32(float x) {
    uint32_t r;
    asm("cvt.rna.tf32.f32 %0, %1;" : "=r"(r) : "f"(x));
    return r;
}
__device__ __forceinline__ void mma_tf32(float* c, const uint32_t* a,
                                         const uint32_t* b) {
    asm volatile(
        "mma.sync.aligned.m16n8k8.row.col.f32.tf32.tf32.f32 "
        "{%0,%1,%2,%3}, {%4,%5,%6,%7}, {%8,%9}, {%0,%1,%2,%3};"
        : "+f"(c[0]), "+f"(c[1]), "+f"(c[2]), "+f"(c[3])
        : "r"(a[0]), "r"(a[1]), "r"(a[2]), "r"(a[3]),
          "r"(b[0]), "r"(b[1]));
}

// ---------------------------------------------------------------------------
// Tiled C = A @ B^T + bias1 (+bias2), fp32 FFMA2 path (precompute GEMMs).
// ---------------------------------------------------------------------------
template <bool GATHER>
__global__ void __launch_bounds__(256, 2)
gemm_kernel(const float* __restrict__ A, const int* __restrict__ idx,
            const float* __restrict__ B, const float* __restrict__ bias1,
            const float* __restrict__ bias2, float* __restrict__ C,
            int N, int K) {
    __shared__ __align__(16) float As[32][132];
    __shared__ __align__(16) float Bs[32][132];
    __shared__ int idx_s[128];

    const int tid = threadIdx.x;
    const int tx = tid & 15;
    const int ty = tid >> 4;
    const int mbase = blockIdx.y * 128;
    const int nbase = blockIdx.x * 128;

    if (GATHER) {
        if (tid < 128) idx_s[tid] = idx[mbase + tid];
        __syncthreads();
    }

    unsigned long long acc[8][4];
#pragma unroll
    for (int i = 0; i < 8; i++)
#pragma unroll
        for (int j = 0; j < 4; j++) acc[i][j] = 0ull;

    for (int kc = 0; kc < K; kc += 32) {
#pragma unroll
        for (int l = 0; l < 4; l++) {
            int f = tid + l * 256;
            int row = f >> 3;
            int c4 = f & 7;
            const float* ar = GATHER ? (A + (size_t)idx_s[row] * K)
                                     : (A + (size_t)(mbase + row) * K);
            float4 v = *(const float4*)(ar + kc + c4 * 4);
            As[c4 * 4 + 0][row] = v.x;
            As[c4 * 4 + 1][row] = v.y;
            As[c4 * 4 + 2][row] = v.z;
            As[c4 * 4 + 3][row] = v.w;
        }
#pragma unroll
        for (int l = 0; l < 4; l++) {
            int f = tid + l * 256;
            int row = f >> 3;
            int c4 = f & 7;
            const float* br = B + (size_t)(nbase + row) * K;
            float4 v = *(const float4*)(br + kc + c4 * 4);
            Bs[c4 * 4 + 0][row] = v.x;
            Bs[c4 * 4 + 1][row] = v.y;
            Bs[c4 * 4 + 2][row] = v.z;
            Bs[c4 * 4 + 3][row] = v.w;
        }
        __syncthreads();

#pragma unroll
        for (int k = 0; k < 32; k++) {
            float4 a0 = *(const float4*)&As[k][ty * 8];
            float4 a1 = *(const float4*)&As[k][ty * 8 + 4];
            ulonglong2 bA = *(const ulonglong2*)&Bs[k][tx * 8];
            ulonglong2 bB = *(const ulonglong2*)&Bs[k][tx * 8 + 4];
            float av[8] = {a0.x, a0.y, a0.z, a0.w, a1.x, a1.y, a1.z, a1.w};
#pragma unroll
            for (int i = 0; i < 8; i++) {
                unsigned long long ad = dup_f32(av[i]);
                fma_f32x2(acc[i][0], ad, bA.x);
                fma_f32x2(acc[i][1], ad, bA.y);
                fma_f32x2(acc[i][2], ad, bB.x);
                fma_f32x2(acc[i][3], ad, bB.y);
            }
        }
        __syncthreads();
    }

#pragma unroll
    for (int i = 0; i < 8; i++) {
        int m = mbase + ty * 8 + i;
        float* cr = C + (size_t)m * N + nbase + tx * 8;
#pragma unroll
        for (int j = 0; j < 4; j++) {
            float2 v = unpack2(acc[i][j]);
            int n = nbase + tx * 8 + j * 2;
            float b0 = bias1[n], b1 = bias1[n + 1];
            if (bias2) { b0 += bias2[n]; b1 += bias2[n + 1]; }
            cr[j * 2 + 0] = v.x + b0;
            cr[j * 2 + 1] = v.y + b1;
        }
    }
}

// ---------------------------------------------------------------------------
// Logits GEMM on TENSOR CORES (tf32 mma, CVT hoisted into staging) +
// streaming logsumexp. (unchanged — proven R14)
// ---------------------------------------------------------------------------
__global__ void __launch_bounds__(256, 2)
logits_kernel(const float* __restrict__ A,    // hs   [512,1024]
              const float* __restrict__ B,    // Wout [32000,1024]
              const float* __restrict__ bias, // bout [32000]
              float* __restrict__ redm, float* __restrict__ reds) {
    __shared__ __align__(16) float As[32][132];   // tf32 bit patterns
    __shared__ __align__(16) float Bs[32][132];   // tf32 bit patterns
    __shared__ float pm[128][4];
    __shared__ float ps[128][4];

    const int tid = threadIdx.x;
    const int warp = tid >> 5;
    const int lane = tid & 31;
    const int wm = warp & 1;
    const int wn = warp >> 1;
    const int qt = lane & 3;
    const int qr = lane >> 2;
    const int mbase = blockIdx.x * 128;
    const int nbase = blockIdx.y * 128;
    const int K = HV;

    float acc[4][4][4];
#pragma unroll
    for (int f = 0; f < 4; f++)
#pragma unroll
        for (int j = 0; j < 4; j++)
#pragma unroll
            for (int q = 0; q < 4; q++) acc[f][j][q] = 0.f;

    for (int kc = 0; kc < K; kc += 32) {
#pragma unroll
        for (int l = 0; l < 4; l++) {
            int f = tid + l * 256;
            int row = f >> 3;
            int c4 = f & 7;
            const float* ar = A + (size_t)(mbase + row) * K;
            float4 v = *(const float4*)(ar + kc + c4 * 4);
            As[c4 * 4 + 0][row] = __uint_as_float(f2tf32(v.x));
            As[c4 * 4 + 1][row] = __uint_as_float(f2tf32(v.y));
            As[c4 * 4 + 2][row] = __uint_as_float(f2tf32(v.z));
            As[c4 * 4 + 3][row] = __uint_as_float(f2tf32(v.w));
        }
#pragma unroll
        for (int l = 0; l < 4; l++) {
            int f = tid + l * 256;
            int row = f >> 3;
            int c4 = f & 7;
            const float* br = B + (size_t)(nbase + row) * K;
            float4 v = *(const float4*)(br + kc + c4 * 4);
            Bs[c4 * 4 + 0][row] = __uint_as_float(f2tf32(v.x));
            Bs[c4 * 4 + 1][row] = __uint_as_float(f2tf32(v.y));
            Bs[c4 * 4 + 2][row] = __uint_as_float(f2tf32(v.z));
            Bs[c4 * 4 + 3][row] = __uint_as_float(f2tf32(v.w));
        }
        __syncthreads();

#pragma unroll
        for (int ks = 0; ks < 4; ks++) {
            uint32_t bfr[4][2];
#pragma unroll
            for (int j = 0; j < 4; j++) {
                int n0 = wn * 32 + j * 8 + qr;
                bfr[j][0] = __float_as_uint(Bs[ks * 8 + qt][n0]);
                bfr[j][1] = __float_as_uint(Bs[ks * 8 + qt + 4][n0]);
            }
#pragma unroll
            for (int f = 0; f < 4; f++) {
                int m0 = wm * 64 + f * 16 + qr;
                uint32_t afr[4];
                afr[0] = __float_as_uint(As[ks * 8 + qt][m0]);
                afr[1] = __float_as_uint(As[ks * 8 + qt][m0 + 8]);
                afr[2] = __float_as_uint(As[ks * 8 + qt + 4][m0]);
                afr[3] = __float_as_uint(As[ks * 8 + qt + 4][m0 + 8]);
#pragma unroll
                for (int j = 0; j < 4; j++)
                    mma_tf32(acc[f][j], afr, bfr[j]);
            }
        }
        __syncthreads();
    }

    float bj[4][2];
#pragma unroll
    for (int j = 0; j < 4; j++) {
        int col = nbase + wn * 32 + j * 8 + qt * 2;
        bj[j][0] = bias[col];
        bj[j][1] = bias[col + 1];
    }
#pragma unroll
    for (int f = 0; f < 4; f++) {
#pragma unroll
        for (int half = 0; half < 2; half++) {
            float vals[8];
#pragma unroll
            for (int j = 0; j < 4; j++) {
                vals[j * 2 + 0] = acc[f][j][half * 2 + 0] + bj[j][0];
                vals[j * 2 + 1] = acc[f][j][half * 2 + 1] + bj[j][1];
            }
            float mx = vals[0];
#pragma unroll
            for (int v = 1; v < 8; v++) mx = fmaxf(mx, vals[v]);
            mx = fmaxf(mx, __shfl_xor_sync(0xffffffffu, mx, 1));
            mx = fmaxf(mx, __shfl_xor_sync(0xffffffffu, mx, 2));
            float s = 0.f;
#pragma unroll
            for (int v = 0; v < 8; v++) s += __expf(vals[v] - mx);
            s += __shfl_xor_sync(0xffffffffu, s, 1);
            s += __shfl_xor_sync(0xffffffffu, s, 2);
            if (qt == 0) {
                int row = wm * 64 + f * 16 + half * 8 + qr;
                pm[row][wn] = mx;
                ps[row][wn] = s;
            }
        }
    }
    __syncthreads();
    if (tid < 128) {
        float m0 = pm[tid][0], m1 = pm[tid][1];
        float m2 = pm[tid][2], m3 = pm[tid][3];
        float M = fmaxf(fmaxf(m0, m1), fmaxf(m2, m3));
        float S = ps[tid][0] * __expf(m0 - M) + ps[tid][1] * __expf(m1 - M) +
                  ps[tid][2] * __expf(m2 - M) + ps[tid][3] * __expf(m3 - M);
        int m = mbase + tid;
        redm[(size_t)m * NVT + blockIdx.y] = M;
        reds[(size_t)m * NVT + blockIdx.y] = S;
    }
}

// ---------------------------------------------------------------------------
// FUSED persistent LSTM: encoder (t 0..511 from Xe/eWhh) then decoder
// (t 512..1023 from Xd/dWhh) in ONE launch. Phase switch at t=512:
//  - decoder h(0) IS the encoder's final h (flows through hbuf naturally)
//  - decoder c0 = tanh(enc final h), computed inline at t=511
//  - weights reloaded from dWhh after step 511's barrier (register-local)
// Sync (settled): single counter, tid0-only release-RED + tid0 acquire poll,
// now 2-DEEP PIPELINED (2 outstanding polls halve the sampling period while
// keeping counter-line traffic at ~1 req/cyc — the R7/R10 traffic law).
// ---------------------------------------------------------------------------
__global__ void __launch_bounds__(256, 1)
lstm_fused_kernel(const float* __restrict__ eWhh,
                  const float* __restrict__ dWhh,
                  const float* __restrict__ Xe,
                  const float* __restrict__ Xd,
                  float* __restrict__ hs_out) {
    __shared__ __align__(16) float hs_s[HV];
    __shared__ float gates_a[32];
    __shared__ float gates_b[32];

    const int tid = threadIdx.x;
    const int ch0 = blockIdx.x * 8;
    const int warp = tid >> 5;
    const int lane = tid & 31;
    const int r0 = warp * 4;

    ulonglong2 w[4][8];
#pragma unroll
    for (int r = 0; r < 4; r++) {
        int rr = r0 + r;
        int gate = rr >> 3, lc = rr & 7;
        const float* gw = eWhh + (size_t)(gate * HV + ch0 + lc) * HV;
#pragma unroll
        for (int i = 0; i < 8; i++)
            w[r][i] = *(const ulonglong2*)(gw + lane * 4 + i * 128);
    }

    float c_val = 0.f;    // encoder c0 = 0
    __syncthreads();

    unsigned* barp = &g_bar;

    for (int t = 0; t < 2 * SV; t++) {
        const int dec = (t >= SV);
        const int tt = dec ? t - SV : t;
        const float* X = dec ? Xd : Xe;

        float xi, xf, xg, xo;
        if (tid < 8) {
            const float* Xr = X + (size_t)tt * G4 + ch0 + tid;
            xi = Xr[0 * HV];
            xf = Xr[1 * HV];
            xg = Xr[2 * HV];
            xo = Xr[3 * HV];
        }

        float4 hv = __ldcg(((const float4*)(g_hbuf + (t & 1) * HV)) + tid);
        *(float4*)&hs_s[tid * 4] = hv;
        __syncthreads();                              // sync A: h staged

        unsigned long long acc[4][2];
#pragma unroll
        for (int r = 0; r < 4; r++) { acc[r][0] = 0ull; acc[r][1] = 0ull; }
#pragma unroll
        for (int i = 0; i < 8; i++) {
            ulonglong2 h2 = *(const ulonglong2*)&hs_s[lane * 4 + i * 128];
#pragma unroll
            for (int r = 0; r < 4; r++) {
                fma_f32x2(acc[r][0], w[r][i].x, h2.x);
                fma_f32x2(acc[r][1], w[r][i].y, h2.y);
            }
        }
        float v[4];
#pragma unroll
        for (int r = 0; r < 4; r++) {
            float2 a = unpack2(acc[r][0]);
            float2 b = unpack2(acc[r][1]);
            v[r] = (a.x + a.y) + (b.x + b.y);
        }
#pragma unroll
        for (int o = 16; o >= 2; o >>= 1) {
            v[0] += __shfl_xor_sync(0xffffffffu, v[0], o);
            v[1] += __shfl_xor_sync(0xffffffffu, v[1], o);
            v[2] += __shfl_xor_sync(0xffffffffu, v[2], o);
            v[3] += __shfl_xor_sync(0xffffffffu, v[3], o);
        }
        if (lane < 2) {
            float* gs = lane ? gates_b : gates_a;
            gs[r0 + 0] = v[0];
            gs[r0 + 1] = v[1];
            gs[r0 + 2] = v[2];
            gs[r0 + 3] = v[3];
        }
        __syncthreads();                              // sync B: gates ready

        if (tid < 8) {
            int lc = tid;
            float gi = gates_a[0 * 8 + lc] + gates_b[0 * 8 + lc] + xi;
            float gf = gates_a[1 * 8 + lc] + gates_b[1 * 8 + lc] + xf;
            float gg = gates_a[2 * 8 + lc] + gates_b[2 * 8 + lc] + xg;
            float go = gates_a[3 * 8 + lc] + gates_b[3 * 8 + lc] + xo;
            float iv = sigmoid_fast(gi);
            float fv = sigmoid_fast(gf);
            float gv = tanh_fast(gg);
            float ov = sigmoid_fast(go);
            c_val = fv * c_val + iv * gv;
            float hval = ov * tanh_fast(c_val);
            g_hbuf[((t + 1) & 1) * HV + ch0 + lc] = hval;
            if (dec) hs_out[(size_t)tt * HV + ch0 + lc] = hval;
            if (t == SV - 1) c_val = tanhf(hval);     // decoder c0 handoff
        }
        __syncwarp();   // warp-0 h stores HB tid0's release-RED below

        if (tid == 0) {
            asm volatile("red.release.gpu.global.add.u32 [%0], 1;"
                         :: "l"(barp) : "memory");
            unsigned tgt = (unsigned)(t + 1) * gridDim.x;
            unsigned v0, v1, m;
            do {     // 2-deep pipelined poll
                asm volatile("ld.acquire.gpu.global.u32 %0, [%1];"
                             : "=r"(v0) : "l"(barp) : "memory");
                asm volatile("ld.acquire.gpu.global.u32 %0, [%1];"
                             : "=r"(v1) : "l"(barp) : "memory");
                m = v0 > v1 ? v0 : v1;
            } while (m < tgt);
        }
        __syncthreads();                              // sync D: step gate

        if (t == SV - 1) {
            // phase switch: reload weights from dWhh (register-local)
#pragma unroll
            for (int r = 0; r < 4; r++) {
                int rr = r0 + r;
                int gate = rr >> 3, lc = rr & 7;
                const float* gw = dWhh + (size_t)(gate * HV + ch0 + lc) * HV;
#pragma unroll
                for (int i = 0; i < 8; i++)
                    w[r][i] = *(const ulonglong2*)(gw + lane * 4 + i * 128);
            }
        }
    }
}

// ---------------------------------------------------------------------------
// Finalize: one warp per target position t. (unchanged)
// ---------------------------------------------------------------------------
__global__ void finalize_kernel(const int* __restrict__ target,
                                const float* __restrict__ Wout,
                                const float* __restrict__ bout,
                                const float* __restrict__ hs,
                                const float* __restrict__ redm,
                                const float* __restrict__ reds,
                                float* __restrict__ out) {
    int gwarp = (blockIdx.x * blockDim.x + threadIdx.x) >> 5;
    int lane = threadIdx.x & 31;
    if (gwarp >= SV) return;
    int t = gwarp;

    float M = -INFINITY, S = 0.f;
    for (int c = lane; c < NVT; c += 32) {
        float m = redm[(size_t)t * NVT + c];
        float s = reds[(size_t)t * NVT + c];
        float nm = fmaxf(M, m);
        S = S * __expf(M - nm) + s * __expf(m - nm);
        M = nm;
    }
#pragma unroll
    for (int o = 16; o; o >>= 1) {
        float m2 = __shfl_xor_sync(0xffffffffu, M, o);
        float s2 = __shfl_xor_sync(0xffffffffu, S, o);
        float nm = fmaxf(M, m2);
        S = S * __expf(M - nm) + s2 * __expf(m2 - nm);
        M = nm;
    }

    int tg = target[t];
    float dot = 0.f;
    const float* hr = hs + (size_t)t * HV;
    const float* wr = Wout + (size_t)tg * HV;
#pragma unroll
    for (int k = lane * 4; k < HV; k += 128) {
        float4 h4 = *(const float4*)(hr + k);
        float4 w4 = *(const float4*)(wr + k);
        dot += h4.x * w4.x + h4.y * w4.y + h4.z * w4.z + h4.w * w4.w;
    }
#pragma unroll
    for (int o = 16; o; o >>= 1) dot += __shfl_xor_sync(0xffffffffu, dot, o);

    if (lane == 0) out[t] = (M + logf(S)) - (dot + bout[tg]);
}

// ---------------------------------------------------------------------------
extern "C" void kernel_launch(void* const* d_in, const int* in_sizes, int n_in,
                              void* d_out, int out_size) {
    (void)in_sizes; (void)n_in; (void)out_size;
    const int*   src  = (const int*)d_in[0];
    const int*   tgt  = (const int*)d_in[1];
    const float* eEmb = (const float*)d_in[2];
    const float* eWih = (const float*)d_in[3];
    const float* eWhh = (const float*)d_in[4];
    const float* eBih = (const float*)d_in[5];
    const float* eBhh = (const float*)d_in[6];
    const float* dEmb = (const float*)d_in[7];
    const float* dWih = (const float*)d_in[8];
    const float* dWhh = (const float*)d_in[9];
    const float* dBih = (const float*)d_in[10];
    const float* dBhh = (const float*)d_in[11];
    const float* Wout = (const float*)d_in[12];
    const float* bout = (const float*)d_in[13];
    float* out = (float*)d_out;

    float *Xe, *Xd, *hbuf, *hs, *redm, *reds;
    unsigned* bar;
    cudaGetSymbolAddress((void**)&Xe, g_Xe);
    cudaGetSymbolAddress((void**)&Xd, g_Xd);
    cudaGetSymbolAddress((void**)&hbuf, g_hbuf);
    cudaGetSymbolAddress((void**)&hs, g_hs);
    cudaGetSymbolAddress((void**)&redm, g_redm);
    cudaGetSymbolAddress((void**)&reds, g_reds);
    cudaGetSymbolAddress((void**)&bar, g_bar);

    cudaMemsetAsync(hbuf, 0, 2 * HV * sizeof(float));
    cudaMemsetAsync(bar, 0, sizeof(unsigned));

    // Precompute X = embed(tok) @ Wih^T + bih + bhh for both phases (fp32)
    dim3 gX(G4 / 128, SV / 128);   // 32 x 4
    gemm_kernel<true><<<gX, 256>>>(eEmb, src, eWih, eBih, eBhh, Xe, G4, EV);
    gemm_kernel<true><<<gX, 256>>>(dEmb, tgt, dWih, dBih, dBhh, Xd, G4, EV);

    // Fused encoder+decoder recurrence (1024 steps, one launch)
    lstm_fused_kernel<<<128, 256>>>(eWhh, dWhh, Xe, Xd, hs);

    // Logits GEMM on tensor cores + per-tile streaming logsumexp stats.
    dim3 gO(SV / 128, NVT);        // 4 x 250
    logits_kernel<<<gO, 256>>>(hs, Wout, bout, redm, reds);

    // Combine tile stats + target logit -> losses
    finalize_kernel<<<(SV * 32 + 255) / 256, 256>>>(tgt, Wout, bout, hs,
                                                    redm, reds, out);
}

// round 16
// speedup vs baseline: 1.1075x; 1.1075x over previous
#include <cuda_runtime.h>
#include <math.h>
#include <stdint.h>

// Problem constants
#define SV 512      // source length == target length
#define EV 512      // embed dim
#define HV 1024     // hidden dim
#define G4 4096     // 4*H
#define VV 32000    // vocab
#define NVT 250     // number of 128-wide V tiles (32000/128)

// ---------------- scratch (static device globals; no allocation) ----------
__device__ float    g_Xe[SV * G4];      // enc: x@Wih^T + bih + bhh  [512,4096]
__device__ float    g_Xd[SV * G4];      // dec: same
__device__ float    g_hbuf[2 * HV];     // double-buffered h
__device__ float    g_c0[HV];           // decoder initial c = tanh(enc_h)
__device__ float    g_hs[SV * HV];      // decoder hidden states [512,1024]
__device__ float    g_redm[SV * NVT];   // per-(t, vtile) local max
__device__ float    g_reds[SV * NVT];   // per-(t, vtile) local sumexp
__device__ unsigned g_bar;              // single barrier counter

// ---------------- f32x2 packed FMA helpers (Blackwell FFMA2) --------------
__device__ __forceinline__ unsigned long long dup_f32(float x) {
    unsigned long long r;
    asm("mov.b64 %0, {%1, %1};" : "=l"(r) : "f"(x));
    return r;
}
__device__ __forceinline__ void fma_f32x2(unsigned long long& d,
                                          unsigned long long a,
                                          unsigned long long b) {
    asm("fma.rn.f32x2 %0, %1, %2, %0;" : "+l"(d) : "l"(a), "l"(b));
}
__device__ __forceinline__ float2 unpack2(unsigned long long v) {
    float2 r;
    asm("mov.b64 {%0, %1}, %2;" : "=f"(r.x), "=f"(r.y) : "l"(v));
    return r;
}
// ---------------- fast activations (validated R10/R13) --------------------
__device__ __forceinline__ float tanh_fast(float x) {
    float r;
    asm("tanh.approx.f32 %0, %1;" : "=f"(r) : "f"(x));
    return r;
}
__device__ __forceinline__ float sigmoid_fast(float x) {
    return __fdividef(1.f, 1.f + __expf(-x));
}
// ---------------- bf16 tensor-core helpers --------------------------------
// pack two f32 -> bf16x2 (lo = first/even-k element, hi = second/odd-k)
__device__ __forceinline__ uint32_t pack_bf16x2(float lo, float hi) {
    uint32_t r;
    asm("cvt.rn.bf16x2.f32 %0, %1, %2;" : "=r"(r) : "f"(hi), "f"(lo));
    return r;
}
__device__ __forceinline__ void mma_bf16(float* c, const uint32_t* a,
                                         const uint32_t* b) {
    asm volatile(
        "mma.sync.aligned.m16n8k16.row.col.f32.bf16.bf16.f32 "
        "{%0,%1,%2,%3}, {%4,%5,%6,%7}, {%8,%9}, {%0,%1,%2,%3};"
        : "+f"(c[0]), "+f"(c[1]), "+f"(c[2]), "+f"(c[3])
        : "r"(a[0]), "r"(a[1]), "r"(a[2]), "r"(a[3]),
          "r"(b[0]), "r"(b[1]));
}

// ---------------------------------------------------------------------------
// Tiled C = A @ B^T + bias1 (+bias2), fp32 FFMA2 path (precompute GEMMs —
// recurrence inputs must stay exact fp32).
// ---------------------------------------------------------------------------
template <bool GATHER>
__global__ void __launch_bounds__(256, 2)
gemm_kernel(const float* __restrict__ A, const int* __restrict__ idx,
            const float* __restrict__ B, const float* __restrict__ bias1,
            const float* __restrict__ bias2, float* __restrict__ C,
            int N, int K) {
    __shared__ __align__(16) float As[32][132];
    __shared__ __align__(16) float Bs[32][132];
    __shared__ int idx_s[128];

    const int tid = threadIdx.x;
    const int tx = tid & 15;
    const int ty = tid >> 4;
    const int mbase = blockIdx.y * 128;
    const int nbase = blockIdx.x * 128;

    if (GATHER) {
        if (tid < 128) idx_s[tid] = idx[mbase + tid];
        __syncthreads();
    }

    unsigned long long acc[8][4];
#pragma unroll
    for (int i = 0; i < 8; i++)
#pragma unroll
        for (int j = 0; j < 4; j++) acc[i][j] = 0ull;

    for (int kc = 0; kc < K; kc += 32) {
#pragma unroll
        for (int l = 0; l < 4; l++) {
            int f = tid + l * 256;
            int row = f >> 3;
            int c4 = f & 7;
            const float* ar = GATHER ? (A + (size_t)idx_s[row] * K)
                                     : (A + (size_t)(mbase + row) * K);
            float4 v = *(const float4*)(ar + kc + c4 * 4);
            As[c4 * 4 + 0][row] = v.x;
            As[c4 * 4 + 1][row] = v.y;
            As[c4 * 4 + 2][row] = v.z;
            As[c4 * 4 + 3][row] = v.w;
        }
#pragma unroll
        for (int l = 0; l < 4; l++) {
            int f = tid + l * 256;
            int row = f >> 3;
            int c4 = f & 7;
            const float* br = B + (size_t)(nbase + row) * K;
            float4 v = *(const float4*)(br + kc + c4 * 4);
            Bs[c4 * 4 + 0][row] = v.x;
            Bs[c4 * 4 + 1][row] = v.y;
            Bs[c4 * 4 + 2][row] = v.z;
            Bs[c4 * 4 + 3][row] = v.w;
        }
        __syncthreads();

#pragma unroll
        for (int k = 0; k < 32; k++) {
            float4 a0 = *(const float4*)&As[k][ty * 8];
            float4 a1 = *(const float4*)&As[k][ty * 8 + 4];
            ulonglong2 bA = *(const ulonglong2*)&Bs[k][tx * 8];
            ulonglong2 bB = *(const ulonglong2*)&Bs[k][tx * 8 + 4];
            float av[8] = {a0.x, a0.y, a0.z, a0.w, a1.x, a1.y, a1.z, a1.w};
#pragma unroll
            for (int i = 0; i < 8; i++) {
                unsigned long long ad = dup_f32(av[i]);
                fma_f32x2(acc[i][0], ad, bA.x);
                fma_f32x2(acc[i][1], ad, bA.y);
                fma_f32x2(acc[i][2], ad, bB.x);
                fma_f32x2(acc[i][3], ad, bB.y);
            }
        }
        __syncthreads();
    }

#pragma unroll
    for (int i = 0; i < 8; i++) {
        int m = mbase + ty * 8 + i;
        float* cr = C + (size_t)m * N + nbase + tx * 8;
#pragma unroll
        for (int j = 0; j < 4; j++) {
            float2 v = unpack2(acc[i][j]);
            int n = nbase + tx * 8 + j * 2;
            float b0 = bias1[n], b1 = bias1[n + 1];
            if (bias2) { b0 += bias2[n]; b1 += bias2[n + 1]; }
            cr[j * 2 + 0] = v.x + b0;
            cr[j * 2 + 1] = v.y + b1;
        }
    }
}

// ---------------------------------------------------------------------------
// Logits GEMM on TENSOR CORES — bf16 mma.m16n8k16 + streaming logsumexp.
// smem staged as PACKED bf16x2 k-pairs: As2/Bs2[k2][row], stride 132 words
// (bank = 4*qt + qr: bijective onto 0..31 per warp -> conflict-free frags).
// vs tf32 k8 version: LDS count halved, mma count halved, smem halved.
// Target logit in finalize stays exact fp32; logsumexp averages the bf16
// noise (near-zero-mean) -> loss error ~1e-5.
// ---------------------------------------------------------------------------
__global__ void __launch_bounds__(256, 2)
logits_kernel(const float* __restrict__ A,    // hs   [512,1024]
              const float* __restrict__ B,    // Wout [32000,1024]
              const float* __restrict__ bias, // bout [32000]
              float* __restrict__ redm, float* __restrict__ reds) {
    __shared__ __align__(16) uint32_t As2[16][132];  // bf16x2 pairs (k-chunk 32)
    __shared__ __align__(16) uint32_t Bs2[16][132];
    __shared__ float pm[128][4];
    __shared__ float ps[128][4];

    const int tid = threadIdx.x;
    const int warp = tid >> 5;
    const int lane = tid & 31;
    const int wm = warp & 1;          // warp m-slot: 0..1 (64 rows)
    const int wn = warp >> 1;         // warp n-slot: 0..3 (32 cols)
    const int qt = lane & 3;          // thread-in-quad
    const int qr = lane >> 2;         // quad row
    const int mbase = blockIdx.x * 128;
    const int nbase = blockIdx.y * 128;
    const int K = HV;

    float acc[4][4][4];               // [m-frag][n-frag][c0..c3]
#pragma unroll
    for (int f = 0; f < 4; f++)
#pragma unroll
        for (int j = 0; j < 4; j++)
#pragma unroll
            for (int q = 0; q < 4; q++) acc[f][j][q] = 0.f;

    for (int kc = 0; kc < K; kc += 32) {
        // stage A tile: rows 128 x 32 k -> bf16x2 pairs [k2][row]
#pragma unroll
        for (int l = 0; l < 4; l++) {
            int f = tid + l * 256;
            int row = f >> 3;
            int c4 = f & 7;
            const float* ar = A + (size_t)(mbase + row) * K + kc + c4 * 4;
            float4 v = *(const float4*)ar;
            As2[c4 * 2 + 0][row] = pack_bf16x2(v.x, v.y);
            As2[c4 * 2 + 1][row] = pack_bf16x2(v.z, v.w);
        }
#pragma unroll
        for (int l = 0; l < 4; l++) {
            int f = tid + l * 256;
            int row = f >> 3;
            int c4 = f & 7;
            const float* br = B + (size_t)(nbase + row) * K + kc + c4 * 4;
            float4 v = *(const float4*)br;
            Bs2[c4 * 2 + 0][row] = pack_bf16x2(v.x, v.y);
            Bs2[c4 * 2 + 1][row] = pack_bf16x2(v.z, v.w);
        }
        __syncthreads();

        // two k16 steps per 32-k chunk
#pragma unroll
        for (int s = 0; s < 2; s++) {
            uint32_t bfr[4][2];
#pragma unroll
            for (int j = 0; j < 4; j++) {
                int n0 = wn * 32 + j * 8 + qr;
                bfr[j][0] = Bs2[s * 8 + qt][n0];
                bfr[j][1] = Bs2[s * 8 + 4 + qt][n0];
            }
#pragma unroll
            for (int f = 0; f < 4; f++) {
                int m0 = wm * 64 + f * 16 + qr;
                uint32_t afr[4];
                afr[0] = As2[s * 8 + qt][m0];
                afr[1] = As2[s * 8 + qt][m0 + 8];
                afr[2] = As2[s * 8 + 4 + qt][m0];
                afr[3] = As2[s * 8 + 4 + qt][m0 + 8];
#pragma unroll
                for (int j = 0; j < 4; j++)
                    mma_bf16(acc[f][j], afr, bfr[j]);
            }
        }
        __syncthreads();
    }

    // ---- epilogue: per-row (max, sumexp) over this 128-col tile ----
    float bj[4][2];
#pragma unroll
    for (int j = 0; j < 4; j++) {
        int col = nbase + wn * 32 + j * 8 + qt * 2;
        bj[j][0] = bias[col];
        bj[j][1] = bias[col + 1];
    }
#pragma unroll
    for (int f = 0; f < 4; f++) {
#pragma unroll
        for (int half = 0; half < 2; half++) {
            float vals[8];
#pragma unroll
            for (int j = 0; j < 4; j++) {
                vals[j * 2 + 0] = acc[f][j][half * 2 + 0] + bj[j][0];
                vals[j * 2 + 1] = acc[f][j][half * 2 + 1] + bj[j][1];
            }
            float mx = vals[0];
#pragma unroll
            for (int v = 1; v < 8; v++) mx = fmaxf(mx, vals[v]);
            mx = fmaxf(mx, __shfl_xor_sync(0xffffffffu, mx, 1));
            mx = fmaxf(mx, __shfl_xor_sync(0xffffffffu, mx, 2));
            float s = 0.f;
#pragma unroll
            for (int v = 0; v < 8; v++) s += __expf(vals[v] - mx);
            s += __shfl_xor_sync(0xffffffffu, s, 1);
            s += __shfl_xor_sync(0xffffffffu, s, 2);
            if (qt == 0) {
                int row = wm * 64 + f * 16 + half * 8 + qr;
                pm[row][wn] = mx;
                ps[row][wn] = s;
            }
        }
    }
    __syncthreads();
    if (tid < 128) {
        float m0 = pm[tid][0], m1 = pm[tid][1];
        float m2 = pm[tid][2], m3 = pm[tid][3];
        float M = fmaxf(fmaxf(m0, m1), fmaxf(m2, m3));
        float S = ps[tid][0] * __expf(m0 - M) + ps[tid][1] * __expf(m1 - M) +
                  ps[tid][2] * __expf(m2 - M) + ps[tid][3] * __expf(m3 - M);
        int m = mbase + tid;
        redm[(size_t)m * NVT + blockIdx.y] = M;
        reds[(size_t)m * NVT + blockIdx.y] = S;
    }
}

// ---------------------------------------------------------------------------
// Persistent LSTM kernel — exact R14 (proven 2434us). Settled design:
//  * sync: single counter, tid0-only release-RED + tid0-only 1-DEEP poll
//  * h publish: ONE coalesced 8-float store from warp 0 + __syncwarp
//  * weights in registers; 4-round butterfly + gates_a/gates_b partials
// ---------------------------------------------------------------------------
__global__ void __launch_bounds__(256, 1)
lstm_kernel(const float* __restrict__ Whh, const float* __restrict__ X,
            const float* __restrict__ cinit, float* __restrict__ cout_,
            float* __restrict__ hs_out, int steps) {
    __shared__ __align__(16) float hs_s[HV];
    __shared__ float gates_a[32];
    __shared__ float gates_b[32];

    const int tid = threadIdx.x;
    const int ch0 = blockIdx.x * 8;
    const int warp = tid >> 5;
    const int lane = tid & 31;
    const int r0 = warp * 4;

    ulonglong2 w[4][8];
#pragma unroll
    for (int r = 0; r < 4; r++) {
        int rr = r0 + r;
        int gate = rr >> 3, lc = rr & 7;
        const float* gw = Whh + (size_t)(gate * HV + ch0 + lc) * HV;
#pragma unroll
        for (int i = 0; i < 8; i++)
            w[r][i] = *(const ulonglong2*)(gw + lane * 4 + i * 128);
    }

    float c_val = 0.f;
    if (tid < 8) c_val = cinit ? cinit[ch0 + tid] : 0.f;
    __syncthreads();

    unsigned* barp = &g_bar;

    for (int t = 0; t < steps; t++) {
        float xi, xf, xg, xo;
        if (tid < 8) {
            const float* Xr = X + (size_t)t * G4 + ch0 + tid;
            xi = Xr[0 * HV];
            xf = Xr[1 * HV];
            xg = Xr[2 * HV];
            xo = Xr[3 * HV];
        }

        float4 hv = __ldcg(((const float4*)(g_hbuf + (t & 1) * HV)) + tid);
        *(float4*)&hs_s[tid * 4] = hv;
        __syncthreads();                              // sync A: h staged

        unsigned long long acc[4][2];
#pragma unroll
        for (int r = 0; r < 4; r++) { acc[r][0] = 0ull; acc[r][1] = 0ull; }
#pragma unroll
        for (int i = 0; i < 8; i++) {
            ulonglong2 h2 = *(const ulonglong2*)&hs_s[lane * 4 + i * 128];
#pragma unroll
            for (int r = 0; r < 4; r++) {
                fma_f32x2(acc[r][0], w[r][i].x, h2.x);
                fma_f32x2(acc[r][1], w[r][i].y, h2.y);
            }
        }
        float v[4];
#pragma unroll
        for (int r = 0; r < 4; r++) {
            float2 a = unpack2(acc[r][0]);
            float2 b = unpack2(acc[r][1]);
            v[r] = (a.x + a.y) + (b.x + b.y);
        }
#pragma unroll
        for (int o = 16; o >= 2; o >>= 1) {
            v[0] += __shfl_xor_sync(0xffffffffu, v[0], o);
            v[1] += __shfl_xor_sync(0xffffffffu, v[1], o);
            v[2] += __shfl_xor_sync(0xffffffffu, v[2], o);
            v[3] += __shfl_xor_sync(0xffffffffu, v[3], o);
        }
        if (lane < 2) {
            float* gs = lane ? gates_b : gates_a;
            gs[r0 + 0] = v[0];
            gs[r0 + 1] = v[1];
            gs[r0 + 2] = v[2];
            gs[r0 + 3] = v[3];
        }
        __syncthreads();                              // sync B: gates ready

        if (tid < 8) {
            int lc = tid;
            float gi = gates_a[0 * 8 + lc] + gates_b[0 * 8 + lc] + xi;
            float gf = gates_a[1 * 8 + lc] + gates_b[1 * 8 + lc] + xf;
            float gg = gates_a[2 * 8 + lc] + gates_b[2 * 8 + lc] + xg;
            float go = gates_a[3 * 8 + lc] + gates_b[3 * 8 + lc] + xo;
            float iv = sigmoid_fast(gi);
            float fv = sigmoid_fast(gf);
            float gv = tanh_fast(gg);
            float ov = sigmoid_fast(go);
            c_val = fv * c_val + iv * gv;
            float hval = ov * tanh_fast(c_val);
            g_hbuf[((t + 1) & 1) * HV + ch0 + lc] = hval;
            if (hs_out) hs_out[(size_t)t * HV + ch0 + lc] = hval;
            if (cout_ && t == steps - 1) cout_[ch0 + lc] = tanhf(hval);
        }
        __syncwarp();   // warp-0 h stores HB tid0's release-RED below

        if (tid == 0) {
            asm volatile("red.release.gpu.global.add.u32 [%0], 1;"
                         :: "l"(barp) : "memory");
            unsigned tgt = (unsigned)(t + 1) * gridDim.x;
            unsigned vv;
            do {
                asm volatile("ld.acquire.gpu.global.u32 %0, [%1];"
                             : "=r"(vv) : "l"(barp) : "memory");
            } while (vv < tgt);
        }
        __syncthreads();                              // sync D: step gate
    }
}

// ---------------------------------------------------------------------------
// Finalize: one warp per target position t. (unchanged)
// ---------------------------------------------------------------------------
__global__ void finalize_kernel(const int* __restrict__ target,
                                const float* __restrict__ Wout,
                                const float* __restrict__ bout,
                                const float* __restrict__ hs,
                                const float* __restrict__ redm,
                                const float* __restrict__ reds,
                                float* __restrict__ out) {
    int gwarp = (blockIdx.x * blockDim.x + threadIdx.x) >> 5;
    int lane = threadIdx.x & 31;
    if (gwarp >= SV) return;
    int t = gwarp;

    float M = -INFINITY, S = 0.f;
    for (int c = lane; c < NVT; c += 32) {
        float m = redm[(size_t)t * NVT + c];
        float s = reds[(size_t)t * NVT + c];
        float nm = fmaxf(M, m);
        S = S * __expf(M - nm) + s * __expf(m - nm);
        M = nm;
    }
#pragma unroll
    for (int o = 16; o; o >>= 1) {
        float m2 = __shfl_xor_sync(0xffffffffu, M, o);
        float s2 = __shfl_xor_sync(0xffffffffu, S, o);
        float nm = fmaxf(M, m2);
        S = S * __expf(M - nm) + s2 * __expf(m2 - nm);
        M = nm;
    }

    int tg = target[t];
    float dot = 0.f;
    const float* hr = hs + (size_t)t * HV;
    const float* wr = Wout + (size_t)tg * HV;
#pragma unroll
    for (int k = lane * 4; k < HV; k += 128) {
        float4 h4 = *(const float4*)(hr + k);
        float4 w4 = *(const float4*)(wr + k);
        dot += h4.x * w4.x + h4.y * w4.y + h4.z * w4.z + h4.w * w4.w;
    }
#pragma unroll
    for (int o = 16; o; o >>= 1) dot += __shfl_xor_sync(0xffffffffu, dot, o);

    if (lane == 0) out[t] = (M + logf(S)) - (dot + bout[tg]);
}

// ---------------------------------------------------------------------------
extern "C" void kernel_launch(void* const* d_in, const int* in_sizes, int n_in,
                              void* d_out, int out_size) {
    (void)in_sizes; (void)n_in; (void)out_size;
    const int*   src  = (const int*)d_in[0];
    const int*   tgt  = (const int*)d_in[1];
    const float* eEmb = (const float*)d_in[2];
    const float* eWih = (const float*)d_in[3];
    const float* eWhh = (const float*)d_in[4];
    const float* eBih = (const float*)d_in[5];
    const float* eBhh = (const float*)d_in[6];
    const float* dEmb = (const float*)d_in[7];
    const float* dWih = (const float*)d_in[8];
    const float* dWhh = (const float*)d_in[9];
    const float* dBih = (const float*)d_in[10];
    const float* dBhh = (const float*)d_in[11];
    const float* Wout = (const float*)d_in[12];
    const float* bout = (const float*)d_in[13];
    float* out = (float*)d_out;

    float *Xe, *Xd, *hbuf, *c0, *hs, *redm, *reds;
    unsigned* bar;
    cudaGetSymbolAddress((void**)&Xe, g_Xe);
    cudaGetSymbolAddress((void**)&Xd, g_Xd);
    cudaGetSymbolAddress((void**)&hbuf, g_hbuf);
    cudaGetSymbolAddress((void**)&c0, g_c0);
    cudaGetSymbolAddress((void**)&hs, g_hs);
    cudaGetSymbolAddress((void**)&redm, g_redm);
    cudaGetSymbolAddress((void**)&reds, g_reds);
    cudaGetSymbolAddress((void**)&bar, g_bar);

    cudaMemsetAsync(hbuf, 0, 2 * HV * sizeof(float));
    cudaMemsetAsync(bar, 0, sizeof(unsigned));

    // Precompute X = embed(tok) @ Wih^T + bih + bhh for both phases (fp32)
    dim3 gX(G4 / 128, SV / 128);   // 32 x 4
    gemm_kernel<true><<<gX, 256>>>(eEmb, src, eWih, eBih, eBhh, Xe, G4, EV);
    gemm_kernel<true><<<gX, 256>>>(dEmb, tgt, dWih, dBih, dBhh, Xd, G4, EV);

    // Encoder recurrence (h0=c0=0). Final h lands in hbuf[0]; c0 = tanh(h).
    lstm_kernel<<<128, 256>>>(eWhh, Xe, nullptr, c0, nullptr, SV);
    cudaMemsetAsync(bar, 0, sizeof(unsigned));
    // Decoder recurrence, teacher-forced; stores all h_t.
    lstm_kernel<<<128, 256>>>(dWhh, Xd, c0, nullptr, hs, SV);

    // Logits GEMM on bf16 tensor cores + per-tile streaming logsumexp stats.
    dim3 gO(SV / 128, NVT);        // 4 x 250
    logits_kernel<<<gO, 256>>>(hs, Wout, bout, redm, reds);

    // Combine tile stats + target logit -> losses
    finalize_kernel<<<(SV * 32 + 255) / 256, 256>>>(tgt, Wout, bout, hs,
                                                    redm, reds, out);
}

// round 17
// speedup vs baseline: 1.1522x; 1.0403x over previous
#include <cuda_runtime.h>
#include <math.h>
#include <stdint.h>

// Problem constants
#define SV 512      // source length == target length
#define EV 512      // embed dim
#define HV 1024     // hidden dim
#define G4 4096     // 4*H
#define VV 32000    // vocab
#define NVT 250     // number of 128-wide V tiles (32000/128)

// ---------------- scratch (static device globals; no allocation) ----------
__device__ float    g_Xe[SV * G4];      // enc: x@Wih^T + bih + bhh  [512,4096]
__device__ float    g_Xd[SV * G4];      // dec: same
__device__ float    g_hbuf[2 * HV];     // double-buffered h
__device__ float    g_c0[HV];           // decoder initial c = tanh(enc_h)
__device__ float    g_hs[SV * HV];      // decoder hidden states [512,1024]
__device__ float    g_redm[SV * NVT];   // per-(t, vtile) local max
__device__ float    g_reds[SV * NVT];   // per-(t, vtile) local sumexp
__device__ unsigned g_bar;              // single barrier counter

// ---------------- f32x2 packed FMA helpers (Blackwell FFMA2) --------------
__device__ __forceinline__ unsigned long long dup_f32(float x) {
    unsigned long long r;
    asm("mov.b64 %0, {%1, %1};" : "=l"(r) : "f"(x));
    return r;
}
__device__ __forceinline__ void fma_f32x2(unsigned long long& d,
                                          unsigned long long a,
                                          unsigned long long b) {
    asm("fma.rn.f32x2 %0, %1, %2, %0;" : "+l"(d) : "l"(a), "l"(b));
}
__device__ __forceinline__ float2 unpack2(unsigned long long v) {
    float2 r;
    asm("mov.b64 {%0, %1}, %2;" : "=f"(r.x), "=f"(r.y) : "l"(v));
    return r;
}
// ---------------- fast activations (validated R10/R13) --------------------
__device__ __forceinline__ float tanh_fast(float x) {
    float r;
    asm("tanh.approx.f32 %0, %1;" : "=f"(r) : "f"(x));
    return r;
}
__device__ __forceinline__ float sigmoid_fast(float x) {
    return __fdividef(1.f, 1.f + __expf(-x));
}
// ---------------- bf16 tensor-core helpers --------------------------------
__device__ __forceinline__ uint32_t pack_bf16x2(float lo, float hi) {
    uint32_t r;
    asm("cvt.rn.bf16x2.f32 %0, %1, %2;" : "=r"(r) : "f"(hi), "f"(lo));
    return r;
}
__device__ __forceinline__ void mma_bf16(float* c, const uint32_t* a,
                                         const uint32_t* b) {
    asm volatile(
        "mma.sync.aligned.m16n8k16.row.col.f32.bf16.bf16.f32 "
        "{%0,%1,%2,%3}, {%4,%5,%6,%7}, {%8,%9}, {%0,%1,%2,%3};"
        : "+f"(c[0]), "+f"(c[1]), "+f"(c[2]), "+f"(c[3])
        : "r"(a[0]), "r"(a[1]), "r"(a[2]), "r"(a[3]),
          "r"(b[0]), "r"(b[1]));
}

// ---------------------------------------------------------------------------
// Precompute GEMM on bf16 TENSOR CORES: X = gather(emb) @ Wih^T + bih + bhh.
// Same staging + fragment mapping as the (proven) logits kernel; fp32 store.
// M=512 (tokens), N=4096 (gate rows), K=512 (embed dim).
// grid: (N/128, M/128) = (32, 4); 256 threads; warp tile 64x32.
// ---------------------------------------------------------------------------
__global__ void __launch_bounds__(256, 2)
xprep_kernel(const float* __restrict__ emb,   // [V, EV]
             const int* __restrict__ idx,     // [SV]
             const float* __restrict__ B,     // Wih [G4, EV]
             const float* __restrict__ bias1, // bih
             const float* __restrict__ bias2, // bhh
             float* __restrict__ C) {         // X [SV, G4]
    __shared__ __align__(16) uint32_t As2[16][132];  // bf16x2 pairs
    __shared__ __align__(16) uint32_t Bs2[16][132];
    __shared__ int idx_s[128];

    const int tid = threadIdx.x;
    const int warp = tid >> 5;
    const int lane = tid & 31;
    const int wm = warp & 1;
    const int wn = warp >> 1;
    const int qt = lane & 3;
    const int qr = lane >> 2;
    const int mbase = blockIdx.y * 128;
    const int nbase = blockIdx.x * 128;
    const int K = EV;
    const int N = G4;

    if (tid < 128) idx_s[tid] = idx[mbase + tid];
    __syncthreads();

    float acc[4][4][4];
#pragma unroll
    for (int f = 0; f < 4; f++)
#pragma unroll
        for (int j = 0; j < 4; j++)
#pragma unroll
            for (int q = 0; q < 4; q++) acc[f][j][q] = 0.f;

    for (int kc = 0; kc < K; kc += 32) {
#pragma unroll
        for (int l = 0; l < 4; l++) {
            int f = tid + l * 256;
            int row = f >> 3;
            int c4 = f & 7;
            const float* ar = emb + (size_t)idx_s[row] * K + kc + c4 * 4;
            float4 v = *(const float4*)ar;
            As2[c4 * 2 + 0][row] = pack_bf16x2(v.x, v.y);
            As2[c4 * 2 + 1][row] = pack_bf16x2(v.z, v.w);
        }
#pragma unroll
        for (int l = 0; l < 4; l++) {
            int f = tid + l * 256;
            int row = f >> 3;
            int c4 = f & 7;
            const float* br = B + (size_t)(nbase + row) * K + kc + c4 * 4;
            float4 v = *(const float4*)br;
            Bs2[c4 * 2 + 0][row] = pack_bf16x2(v.x, v.y);
            Bs2[c4 * 2 + 1][row] = pack_bf16x2(v.z, v.w);
        }
        __syncthreads();

#pragma unroll
        for (int s = 0; s < 2; s++) {
            uint32_t bfr[4][2];
#pragma unroll
            for (int j = 0; j < 4; j++) {
                int n0 = wn * 32 + j * 8 + qr;
                bfr[j][0] = Bs2[s * 8 + qt][n0];
                bfr[j][1] = Bs2[s * 8 + 4 + qt][n0];
            }
#pragma unroll
            for (int f = 0; f < 4; f++) {
                int m0 = wm * 64 + f * 16 + qr;
                uint32_t afr[4];
                afr[0] = As2[s * 8 + qt][m0];
                afr[1] = As2[s * 8 + qt][m0 + 8];
                afr[2] = As2[s * 8 + 4 + qt][m0];
                afr[3] = As2[s * 8 + 4 + qt][m0 + 8];
#pragma unroll
                for (int j = 0; j < 4; j++)
                    mma_bf16(acc[f][j], afr, bfr[j]);
            }
        }
        __syncthreads();
    }

    // epilogue: fp32 store with bias1+bias2 (frag mapping == logits epilogue)
#pragma unroll
    for (int j = 0; j < 4; j++) {
        int n0 = nbase + wn * 32 + j * 8 + qt * 2;
        float b0 = bias1[n0] + bias2[n0];
        float b1 = bias1[n0 + 1] + bias2[n0 + 1];
#pragma unroll
        for (int f = 0; f < 4; f++) {
            int m0 = mbase + wm * 64 + f * 16 + qr;
            float2 v0 = make_float2(acc[f][j][0] + b0, acc[f][j][1] + b1);
            float2 v1 = make_float2(acc[f][j][2] + b0, acc[f][j][3] + b1);
            *(float2*)(C + (size_t)m0 * N + n0) = v0;
            *(float2*)(C + (size_t)(m0 + 8) * N + n0) = v1;
        }
    }
}

// ---------------------------------------------------------------------------
// Logits GEMM on TENSOR CORES — bf16 mma.m16n8k16 + streaming logsumexp.
// (unchanged — proven R16: 2285us total, rel_err 7.8e-8)
// ---------------------------------------------------------------------------
__global__ void __launch_bounds__(256, 2)
logits_kernel(const float* __restrict__ A,    // hs   [512,1024]
              const float* __restrict__ B,    // Wout [32000,1024]
              const float* __restrict__ bias, // bout [32000]
              float* __restrict__ redm, float* __restrict__ reds) {
    __shared__ __align__(16) uint32_t As2[16][132];
    __shared__ __align__(16) uint32_t Bs2[16][132];
    __shared__ float pm[128][4];
    __shared__ float ps[128][4];

    const int tid = threadIdx.x;
    const int warp = tid >> 5;
    const int lane = tid & 31;
    const int wm = warp & 1;
    const int wn = warp >> 1;
    const int qt = lane & 3;
    const int qr = lane >> 2;
    const int mbase = blockIdx.x * 128;
    const int nbase = blockIdx.y * 128;
    const int K = HV;

    float acc[4][4][4];
#pragma unroll
    for (int f = 0; f < 4; f++)
#pragma unroll
        for (int j = 0; j < 4; j++)
#pragma unroll
            for (int q = 0; q < 4; q++) acc[f][j][q] = 0.f;

    for (int kc = 0; kc < K; kc += 32) {
#pragma unroll
        for (int l = 0; l < 4; l++) {
            int f = tid + l * 256;
            int row = f >> 3;
            int c4 = f & 7;
            const float* ar = A + (size_t)(mbase + row) * K + kc + c4 * 4;
            float4 v = *(const float4*)ar;
            As2[c4 * 2 + 0][row] = pack_bf16x2(v.x, v.y);
            As2[c4 * 2 + 1][row] = pack_bf16x2(v.z, v.w);
        }
#pragma unroll
        for (int l = 0; l < 4; l++) {
            int f = tid + l * 256;
            int row = f >> 3;
            int c4 = f & 7;
            const float* br = B + (size_t)(nbase + row) * K + kc + c4 * 4;
            float4 v = *(const float4*)br;
            Bs2[c4 * 2 + 0][row] = pack_bf16x2(v.x, v.y);
            Bs2[c4 * 2 + 1][row] = pack_bf16x2(v.z, v.w);
        }
        __syncthreads();

#pragma unroll
        for (int s = 0; s < 2; s++) {
            uint32_t bfr[4][2];
#pragma unroll
            for (int j = 0; j < 4; j++) {
                int n0 = wn * 32 + j * 8 + qr;
                bfr[j][0] = Bs2[s * 8 + qt][n0];
                bfr[j][1] = Bs2[s * 8 + 4 + qt][n0];
            }
#pragma unroll
            for (int f = 0; f < 4; f++) {
                int m0 = wm * 64 + f * 16 + qr;
                uint32_t afr[4];
                afr[0] = As2[s * 8 + qt][m0];
                afr[1] = As2[s * 8 + qt][m0 + 8];
                afr[2] = As2[s * 8 + 4 + qt][m0];
                afr[3] = As2[s * 8 + 4 + qt][m0 + 8];
#pragma unroll
                for (int j = 0; j < 4; j++)
                    mma_bf16(acc[f][j], afr, bfr[j]);
            }
        }
        __syncthreads();
    }

    float bj[4][2];
#pragma unroll
    for (int j = 0; j < 4; j++) {
        int col = nbase + wn * 32 + j * 8 + qt * 2;
        bj[j][0] = bias[col];
        bj[j][1] = bias[col + 1];
    }
#pragma unroll
    for (int f = 0; f < 4; f++) {
#pragma unroll
        for (int half = 0; half < 2; half++) {
            float vals[8];
#pragma unroll
            for (int j = 0; j < 4; j++) {
                vals[j * 2 + 0] = acc[f][j][half * 2 + 0] + bj[j][0];
                vals[j * 2 + 1] = acc[f][j][half * 2 + 1] + bj[j][1];
            }
            float mx = vals[0];
#pragma unroll
            for (int v = 1; v < 8; v++) mx = fmaxf(mx, vals[v]);
            mx = fmaxf(mx, __shfl_xor_sync(0xffffffffu, mx, 1));
            mx = fmaxf(mx, __shfl_xor_sync(0xffffffffu, mx, 2));
            float s = 0.f;
#pragma unroll
            for (int v = 0; v < 8; v++) s += __expf(vals[v] - mx);
            s += __shfl_xor_sync(0xffffffffu, s, 1);
            s += __shfl_xor_sync(0xffffffffu, s, 2);
            if (qt == 0) {
                int row = wm * 64 + f * 16 + half * 8 + qr;
                pm[row][wn] = mx;
                ps[row][wn] = s;
            }
        }
    }
    __syncthreads();
    if (tid < 128) {
        float m0 = pm[tid][0], m1 = pm[tid][1];
        float m2 = pm[tid][2], m3 = pm[tid][3];
        float M = fmaxf(fmaxf(m0, m1), fmaxf(m2, m3));
        float S = ps[tid][0] * __expf(m0 - M) + ps[tid][1] * __expf(m1 - M) +
                  ps[tid][2] * __expf(m2 - M) + ps[tid][3] * __expf(m3 - M);
        int m = mbase + tid;
        redm[(size_t)m * NVT + blockIdx.y] = M;
        reds[(size_t)m * NVT + blockIdx.y] = S;
    }
}

// ---------------------------------------------------------------------------
// Persistent LSTM kernel — exact R14/R16 (proven). Settled design:
//  * sync: single counter, tid0-only release-RED + tid0-only 1-DEEP poll
//  * h publish: ONE coalesced 8-float store from warp 0 + __syncwarp
//  * weights in registers; 4-round butterfly + gates_a/gates_b partials
// ---------------------------------------------------------------------------
__global__ void __launch_bounds__(256, 1)
lstm_kernel(const float* __restrict__ Whh, const float* __restrict__ X,
            const float* __restrict__ cinit, float* __restrict__ cout_,
            float* __restrict__ hs_out, int steps) {
    __shared__ __align__(16) float hs_s[HV];
    __shared__ float gates_a[32];
    __shared__ float gates_b[32];

    const int tid = threadIdx.x;
    const int ch0 = blockIdx.x * 8;
    const int warp = tid >> 5;
    const int lane = tid & 31;
    const int r0 = warp * 4;

    ulonglong2 w[4][8];
#pragma unroll
    for (int r = 0; r < 4; r++) {
        int rr = r0 + r;
        int gate = rr >> 3, lc = rr & 7;
        const float* gw = Whh + (size_t)(gate * HV + ch0 + lc) * HV;
#pragma unroll
        for (int i = 0; i < 8; i++)
            w[r][i] = *(const ulonglong2*)(gw + lane * 4 + i * 128);
    }

    float c_val = 0.f;
    if (tid < 8) c_val = cinit ? cinit[ch0 + tid] : 0.f;
    __syncthreads();

    unsigned* barp = &g_bar;

    for (int t = 0; t < steps; t++) {
        float xi, xf, xg, xo;
        if (tid < 8) {
            const float* Xr = X + (size_t)t * G4 + ch0 + tid;
            xi = Xr[0 * HV];
            xf = Xr[1 * HV];
            xg = Xr[2 * HV];
            xo = Xr[3 * HV];
        }

        float4 hv = __ldcg(((const float4*)(g_hbuf + (t & 1) * HV)) + tid);
        *(float4*)&hs_s[tid * 4] = hv;
        __syncthreads();                              // sync A: h staged

        unsigned long long acc[4][2];
#pragma unroll
        for (int r = 0; r < 4; r++) { acc[r][0] = 0ull; acc[r][1] = 0ull; }
#pragma unroll
        for (int i = 0; i < 8; i++) {
            ulonglong2 h2 = *(const ulonglong2*)&hs_s[lane * 4 + i * 128];
#pragma unroll
            for (int r = 0; r < 4; r++) {
                fma_f32x2(acc[r][0], w[r][i].x, h2.x);
                fma_f32x2(acc[r][1], w[r][i].y, h2.y);
            }
        }
        float v[4];
#pragma unroll
        for (int r = 0; r < 4; r++) {
            float2 a = unpack2(acc[r][0]);
            float2 b = unpack2(acc[r][1]);
            v[r] = (a.x + a.y) + (b.x + b.y);
        }
#pragma unroll
        for (int o = 16; o >= 2; o >>= 1) {
            v[0] += __shfl_xor_sync(0xffffffffu, v[0], o);
            v[1] += __shfl_xor_sync(0xffffffffu, v[1], o);
            v[2] += __shfl_xor_sync(0xffffffffu, v[2], o);
            v[3] += __shfl_xor_sync(0xffffffffu, v[3], o);
        }
        if (lane < 2) {
            float* gs = lane ? gates_b : gates_a;
            gs[r0 + 0] = v[0];
            gs[r0 + 1] = v[1];
            gs[r0 + 2] = v[2];
            gs[r0 + 3] = v[3];
        }
        __syncthreads();                              // sync B: gates ready

        if (tid < 8) {
            int lc = tid;
            float gi = gates_a[0 * 8 + lc] + gates_b[0 * 8 + lc] + xi;
            float gf = gates_a[1 * 8 + lc] + gates_b[1 * 8 + lc] + xf;
            float gg = gates_a[2 * 8 + lc] + gates_b[2 * 8 + lc] + xg;
            float go = gates_a[3 * 8 + lc] + gates_b[3 * 8 + lc] + xo;
            float iv = sigmoid_fast(gi);
            float fv = sigmoid_fast(gf);
            float gv = tanh_fast(gg);
            float ov = sigmoid_fast(go);
            c_val = fv * c_val + iv * gv;
            float hval = ov * tanh_fast(c_val);
            g_hbuf[((t + 1) & 1) * HV + ch0 + lc] = hval;
            if (hs_out) hs_out[(size_t)t * HV + ch0 + lc] = hval;
            if (cout_ && t == steps - 1) cout_[ch0 + lc] = tanhf(hval);
        }
        __syncwarp();   // warp-0 h stores HB tid0's release-RED below

        if (tid == 0) {
            asm volatile("red.release.gpu.global.add.u32 [%0], 1;"
                         :: "l"(barp) : "memory");
            unsigned tgt = (unsigned)(t + 1) * gridDim.x;
            unsigned vv;
            do {
                asm volatile("ld.acquire.gpu.global.u32 %0, [%1];"
                             : "=r"(vv) : "l"(barp) : "memory");
            } while (vv < tgt);
        }
        __syncthreads();                              // sync D: step gate
    }
}

// ---------------------------------------------------------------------------
// Finalize: one warp per target position t. (unchanged)
// ---------------------------------------------------------------------------
__global__ void finalize_kernel(const int* __restrict__ target,
                                const float* __restrict__ Wout,
                                const float* __restrict__ bout,
                                const float* __restrict__ hs,
                                const float* __restrict__ redm,
                                const float* __restrict__ reds,
                                float* __restrict__ out) {
    int gwarp = (blockIdx.x * blockDim.x + threadIdx.x) >> 5;
    int lane = threadIdx.x & 31;
    if (gwarp >= SV) return;
    int t = gwarp;

    float M = -INFINITY, S = 0.f;
    for (int c = lane; c < NVT; c += 32) {
        float m = redm[(size_t)t * NVT + c];
        float s = reds[(size_t)t * NVT + c];
        float nm = fmaxf(M, m);
        S = S * __expf(M - nm) + s * __expf(m - nm);
        M = nm;
    }
#pragma unroll
    for (int o = 16; o; o >>= 1) {
        float m2 = __shfl_xor_sync(0xffffffffu, M, o);
        float s2 = __shfl_xor_sync(0xffffffffu, S, o);
        float nm = fmaxf(M, m2);
        S = S * __expf(M - nm) + s2 * __expf(m2 - nm);
        M = nm;
    }

    int tg = target[t];
    float dot = 0.f;
    const float* hr = hs + (size_t)t * HV;
    const float* wr = Wout + (size_t)tg * HV;
#pragma unroll
    for (int k = lane * 4; k < HV; k += 128) {
        float4 h4 = *(const float4*)(hr + k);
        float4 w4 = *(const float4*)(wr + k);
        dot += h4.x * w4.x + h4.y * w4.y + h4.z * w4.z + h4.w * w4.w;
    }
#pragma unroll
    for (int o = 16; o; o >>= 1) dot += __shfl_xor_sync(0xffffffffu, dot, o);

    if (lane == 0) out[t] = (M + logf(S)) - (dot + bout[tg]);
}

// ---------------------------------------------------------------------------
extern "C" void kernel_launch(void* const* d_in, const int* in_sizes, int n_in,
                              void* d_out, int out_size) {
    (void)in_sizes; (void)n_in; (void)out_size;
    const int*   src  = (const int*)d_in[0];
    const int*   tgt  = (const int*)d_in[1];
    const float* eEmb = (const float*)d_in[2];
    const float* eWih = (const float*)d_in[3];
    const float* eWhh = (const float*)d_in[4];
    const float* eBih = (const float*)d_in[5];
    const float* eBhh = (const float*)d_in[6];
    const float* dEmb = (const float*)d_in[7];
    const float* dWih = (const float*)d_in[8];
    const float* dWhh = (const float*)d_in[9];
    const float* dBih = (const float*)d_in[10];
    const float* dBhh = (const float*)d_in[11];
    const float* Wout = (const float*)d_in[12];
    const float* bout = (const float*)d_in[13];
    float* out = (float*)d_out;

    float *Xe, *Xd, *hbuf, *c0, *hs, *redm, *reds;
    unsigned* bar;
    cudaGetSymbolAddress((void**)&Xe, g_Xe);
    cudaGetSymbolAddress((void**)&Xd, g_Xd);
    cudaGetSymbolAddress((void**)&hbuf, g_hbuf);
    cudaGetSymbolAddress((void**)&c0, g_c0);
    cudaGetSymbolAddress((void**)&hs, g_hs);
    cudaGetSymbolAddress((void**)&redm, g_redm);
    cudaGetSymbolAddress((void**)&reds, g_reds);
    cudaGetSymbolAddress((void**)&bar, g_bar);

    cudaMemsetAsync(hbuf, 0, 2 * HV * sizeof(float));
    cudaMemsetAsync(bar, 0, sizeof(unsigned));

    // Precompute X = embed(tok) @ Wih^T + bih + bhh — bf16 tensor cores
    dim3 gX(G4 / 128, SV / 128);   // 32 x 4
    xprep_kernel<<<gX, 256>>>(eEmb, src, eWih, eBih, eBhh, Xe);
    xprep_kernel<<<gX, 256>>>(dEmb, tgt, dWih, dBih, dBhh, Xd);

    // Encoder recurrence (h0=c0=0). Final h lands in hbuf[0]; c0 = tanh(h).
    lstm_kernel<<<128, 256>>>(eWhh, Xe, nullptr, c0, nullptr, SV);
    cudaMemsetAsync(bar, 0, sizeof(unsigned));
    // Decoder recurrence, teacher-forced; stores all h_t.
    lstm_kernel<<<128, 256>>>(dWhh, Xd, c0, nullptr, hs, SV);

    // Logits GEMM on bf16 tensor cores + per-tile streaming logsumexp stats.
    dim3 gO(SV / 128, NVT);        // 4 x 250
    logits_kernel<<<gO, 256>>>(hs, Wout, bout, redm, reds);

    // Combine tile stats + target logit -> losses
    finalize_kernel<<<(SV * 32 + 255) / 256, 256>>>(tgt, Wout, bout, hs,
                                                    redm, reds, out);
}